// round 16
// baseline (speedup 1.0000x reference)
#include <cuda_runtime.h>
#include <cuda_bf16.h>
#include <math.h>
#include <stdint.h>

#define Bn   32
#define Sn   512
#define Dn   1024
#define Hn   16
#define DKn  64
#define BH   (Bn*Hn)                 // 512
#define Mtot (Bn*Sn)                 // 16384
#define CTX_ELEMS (Bn*Sn*Dn)         // 16,777,216
#define ATT_ELEMS ((size_t)Bn*Hn*Sn*Sn) // 134,217,728

// Scratch (allocation-free per harness rules)
__device__ float g_attn_fallback[ATT_ELEMS];
// bf16 hi/lo splits
__device__ __nv_bfloat16 g_xb0[CTX_ELEMS];
__device__ __nv_bfloat16 g_xb1[CTX_ELEMS];
__device__ __nv_bfloat16 g_wb0[3*Dn*Dn];
__device__ __nv_bfloat16 g_wb1[3*Dn*Dn];
__device__ __nv_bfloat16 g_qb0[CTX_ELEMS];
__device__ __nv_bfloat16 g_qb1[CTX_ELEMS];
__device__ __nv_bfloat16 g_kb0[CTX_ELEMS];
__device__ __nv_bfloat16 g_kb1[CTX_ELEMS];
__device__ __nv_bfloat16 g_vt0[CTX_ELEMS];   // V^T: [bh][dk=64][s=512]
__device__ __nv_bfloat16 g_vt1[CTX_ELEMS];

// ---------------- mma.sync bf16 (non-'a' tensor path, works on sm_103) -----
__device__ __forceinline__ void mma_bf16(float4& d, const uint32_t* a,
                                         uint32_t b0, uint32_t b1) {
    asm volatile(
        "mma.sync.aligned.m16n8k16.row.col.f32.bf16.bf16.f32 "
        "{%0,%1,%2,%3},{%4,%5,%6,%7},{%8,%9},{%0,%1,%2,%3};"
        : "+f"(d.x), "+f"(d.y), "+f"(d.z), "+f"(d.w)
        : "r"(a[0]), "r"(a[1]), "r"(a[2]), "r"(a[3]), "r"(b0), "r"(b1));
}

__device__ __forceinline__ void bsplit(float v, __nv_bfloat16& h, __nv_bfloat16& l) {
    h = __float2bfloat16(v);
    l = __float2bfloat16(v - __bfloat162float(h));
}
__device__ __forceinline__ uint32_t packbf(__nv_bfloat16 a, __nv_bfloat16 b) {
    __nv_bfloat162 t(a, b);
    return *(uint32_t*)&t;
}

// ---------------- cp.async helpers (sm_80+, valid on non-'a' sm_103) -------
__device__ __forceinline__ void cpa8(uint32_t saddr, const void* g) {
    asm volatile("cp.async.ca.shared.global [%0], [%1], 8;"
                 :: "r"(saddr), "l"(g) : "memory");
}
#define CP_COMMIT() asm volatile("cp.async.commit_group;" ::: "memory")
#define CP_WAIT0()  asm volatile("cp.async.wait_group 0;" ::: "memory")

// ---------------------------------------------------------------------------
// prep: bf16 hi/lo splits of X and the 3 weight matrices (single kernel)
// ---------------------------------------------------------------------------
#define XF4 (CTX_ELEMS/4)            // 4,194,304 float4 in X
#define WF4 (3*Dn*Dn/4)              // 786,432 float4 in W

__global__ __launch_bounds__(256) void prep_kernel(
    const float* __restrict__ X,
    const float* __restrict__ Wq, const float* __restrict__ Wk, const float* __restrict__ Wv)
{
    size_t i = (size_t)blockIdx.x * 256 + threadIdx.x;
    if (i < XF4) {
        float4 v = ((const float4*)X)[i];
        float f[4] = {v.x, v.y, v.z, v.w};
        __nv_bfloat16 b0[4], b1[4];
#pragma unroll
        for (int k = 0; k < 4; k++) bsplit(f[k], b0[k], b1[k]);
        ((uint32_t*)g_xb0)[i*2]   = packbf(b0[0], b0[1]);
        ((uint32_t*)g_xb0)[i*2+1] = packbf(b0[2], b0[3]);
        ((uint32_t*)g_xb1)[i*2]   = packbf(b1[0], b1[1]);
        ((uint32_t*)g_xb1)[i*2+1] = packbf(b1[2], b1[3]);
    } else {
        size_t j = i - XF4;
        if (j >= WF4) return;
        int z = (int)(j >> 18);
        const float* src = (z == 0) ? Wq : (z == 1) ? Wk : Wv;
        float4 v = ((const float4*)src)[j & 262143];
        float f[4] = {v.x, v.y, v.z, v.w};
        __nv_bfloat16 b0[4], b1[4];
#pragma unroll
        for (int k = 0; k < 4; k++) bsplit(f[k], b0[k], b1[k]);
        ((uint32_t*)g_wb0)[j*2]   = packbf(b0[0], b0[1]);
        ((uint32_t*)g_wb0)[j*2+1] = packbf(b0[2], b0[3]);
        ((uint32_t*)g_wb1)[j*2]   = packbf(b1[0], b1[1]);
        ((uint32_t*)g_wb1)[j*2+1] = packbf(b1[2], b1[3]);
    }
}

// ---------------------------------------------------------------------------
// QKV projection via mma.sync bf16x3: C = X @ W^T + bias
// cp.async double-buffered pipeline. Dead K/V tiles early-exit.
// z=2 (V) writes V^T bf16 hi/lo splits directly (smem-staged transpose).
// ---------------------------------------------------------------------------
#define SA 20   // smem row stride in words

__global__ __launch_bounds__(256, 2) void qkv_mma_kernel(
    const float* __restrict__ bq, const float* __restrict__ bk, const float* __restrict__ bv,
    const int* __restrict__ length)
{
    __shared__ uint32_t As[2][128*SA];
    __shared__ uint32_t Bs[2][128*SA];

    const int tid  = threadIdx.x;
    const int wid  = tid >> 5;
    const int lane = tid & 31;
    const int gid  = lane >> 2;
    const int tig  = lane & 3;
    const int wm   = wid >> 1;
    const int wn   = wid & 1;
    const int z    = blockIdx.z;
    const int bm   = blockIdx.y * 128;
    const int bn   = blockIdx.x * 128;

    if (z >= 1) {
        if ((bm & 511) >= length[bm >> 9]) return;
    }

    const size_t zoff = (size_t)z * Dn * Dn;
    const __nv_bfloat16* w0p = g_wb0 + zoff;
    const __nv_bfloat16* w1p = g_wb1 + zoff;

    const int r0 = tid >> 3;
    const int c4 = tid & 7;

    const uint32_t sA = (uint32_t)__cvta_generic_to_shared(&As[0][0]);
    const uint32_t sB = (uint32_t)__cvta_generic_to_shared(&Bs[0][0]);

    float4 acc[2][8];
#pragma unroll
    for (int mt = 0; mt < 2; mt++)
#pragma unroll
        for (int nt = 0; nt < 8; nt++) acc[mt][nt] = make_float4(0.f, 0.f, 0.f, 0.f);

    // preload stage 0 via cp.async
    {
        const __nv_bfloat16* a = g_xb0 + (size_t)bm * Dn;
        const __nv_bfloat16* w = w0p   + (size_t)bn * Dn;
#pragma unroll
        for (int j = 0; j < 4; j++) {
            int row = r0 + j*32;
            uint32_t wo = (uint32_t)(row*SA + c4*2) * 4;
            cpa8(sA + wo, a + (size_t)row*Dn + c4*4);
            cpa8(sB + wo, w + (size_t)row*Dn + c4*4);
        }
    }
    CP_COMMIT();
    CP_WAIT0();
    __syncthreads();

    for (int it = 0; it < 96; it++) {
        const int cur = it & 1;
        if (it + 1 < 96) {
            int p  = (it + 1) >> 5;
            int kc = ((it + 1) & 31) * 32;
            const __nv_bfloat16* a = ((p == 2) ? g_xb1 : g_xb0) + (size_t)bm * Dn + kc;
            const __nv_bfloat16* w = ((p == 1) ? w1p  : w0p  ) + (size_t)bn * Dn + kc;
            const uint32_t soff = (uint32_t)(((it + 1) & 1) * 2560) * 4;
#pragma unroll
            for (int j = 0; j < 4; j++) {
                int row = r0 + j*32;
                uint32_t wo = soff + (uint32_t)(row*SA + c4*2) * 4;
                cpa8(sA + wo, a + (size_t)row*Dn + c4*4);
                cpa8(sB + wo, w + (size_t)row*Dn + c4*4);
            }
            CP_COMMIT();
        }
#pragma unroll
        for (int s = 0; s < 2; s++) {
            uint32_t af[2][4];
#pragma unroll
            for (int mt = 0; mt < 2; mt++) {
                int base = (wm*32 + mt*16 + gid)*SA + s*8 + tig;
                af[mt][0] = As[cur][base];
                af[mt][1] = As[cur][base + 8*SA];
                af[mt][2] = As[cur][base + 4];
                af[mt][3] = As[cur][base + 8*SA + 4];
            }
#pragma unroll
            for (int nt = 0; nt < 8; nt++) {
                int nb = (wn*64 + nt*8 + gid)*SA + s*8 + tig;
                uint32_t b0 = Bs[cur][nb];
                uint32_t b1 = Bs[cur][nb + 4];
                mma_bf16(acc[0][nt], af[0], b0, b1);
                mma_bf16(acc[1][nt], af[1], b0, b1);
            }
        }
        if (it + 1 < 96) {
            CP_WAIT0();
            __syncthreads();
        }
    }

    const float* bias = (z == 0) ? bq : (z == 1) ? bk : bv;
    if (z == 2) {
        // ---- V: smem-staged transpose -> V^T bf16 hi/lo, coalesced ----
        const int b  = bm >> 9;
        const int s0 = bm & 511;
        const int h0 = bn >> 6;          // heads h0, h0+1
        uint16_t* Vh = (uint16_t*)&As[0][0];          // [64][132] uint16
        uint16_t* Vl = Vh + 64*132;
        __syncthreads();   // all warps done reading As/Bs
#pragma unroll
        for (int ph = 0; ph < 2; ph++) {
            if (wn == ph) {
#pragma unroll
                for (int mt = 0; mt < 2; mt++) {
                    int ra = wm*32 + mt*16 + gid;    // local s-row
                    int rb = ra + 8;
#pragma unroll
                    for (int nt = 0; nt < 8; nt++) {
                        int fl = nt*8 + tig*2;       // local feat (dk) within head
                        int feat = bn + ph*64 + fl;
                        float2 bv2 = *(const float2*)&bias[feat];
                        float vx = acc[mt][nt].x + bv2.x, vy = acc[mt][nt].y + bv2.y;
                        float vz = acc[mt][nt].z + bv2.x, vw = acc[mt][nt].w + bv2.y;
                        __nv_bfloat16 hx,lx,hy,ly,hz,lz,hw,lw;
                        bsplit(vx,hx,lx); bsplit(vy,hy,ly);
                        bsplit(vz,hz,lz); bsplit(vw,hw,lw);
                        Vh[fl*132 + ra]     = *(uint16_t*)&hx;
                        Vl[fl*132 + ra]     = *(uint16_t*)&lx;
                        Vh[(fl+1)*132 + ra] = *(uint16_t*)&hy;
                        Vl[(fl+1)*132 + ra] = *(uint16_t*)&ly;
                        Vh[fl*132 + rb]     = *(uint16_t*)&hz;
                        Vl[fl*132 + rb]     = *(uint16_t*)&lz;
                        Vh[(fl+1)*132 + rb] = *(uint16_t*)&hw;
                        Vl[(fl+1)*132 + rb] = *(uint16_t*)&lw;
                    }
                }
            }
            __syncthreads();
            const size_t base = ((size_t)((b*Hn + h0 + ph))*DKn)*Sn + s0;
#pragma unroll
            for (int j = 0; j < 16; j++) {
                int w = tid + j*256;
                int dk = w >> 6;
                int sw = (w & 63) * 2;
                uint32_t vh = *(uint32_t*)&Vh[dk*132 + sw];
                uint32_t vl = *(uint32_t*)&Vl[dk*132 + sw];
                *(uint32_t*)&g_vt0[base + (size_t)dk*Sn + sw] = vh;
                *(uint32_t*)&g_vt1[base + (size_t)dk*Sn + sw] = vl;
            }
            __syncthreads();
        }
    } else {
        __nv_bfloat16* o0 = (z == 0) ? g_qb0 : g_kb0;
        __nv_bfloat16* o1 = (z == 0) ? g_qb1 : g_kb1;
#pragma unroll
        for (int mt = 0; mt < 2; mt++) {
            int rowa = bm + wm*32 + mt*16 + gid;
            int rowb = rowa + 8;
            int ba = rowa >> 9, sa = rowa & 511;
            int bb2 = rowb >> 9, sb = rowb & 511;
#pragma unroll
            for (int nt = 0; nt < 8; nt++) {
                int feat = bn + wn*64 + nt*8 + tig*2;
                int h = feat >> 6, dk = feat & 63;
                float2 bv2 = *(const float2*)&bias[feat];
                float vx = acc[mt][nt].x + bv2.x, vy = acc[mt][nt].y + bv2.y;
                float vz = acc[mt][nt].z + bv2.x, vw = acc[mt][nt].w + bv2.y;
                __nv_bfloat16 hx,lx,hy,ly,hz,lz,hw,lw;
                bsplit(vx,hx,lx); bsplit(vy,hy,ly); bsplit(vz,hz,lz); bsplit(vw,hw,lw);
                size_t ia = ((size_t)((ba *Hn + h)*Sn + sa))*DKn + dk;
                size_t ib = ((size_t)((bb2*Hn + h)*Sn + sb))*DKn + dk;
                *(uint32_t*)&o0[ia] = packbf(hx,hy);
                *(uint32_t*)&o1[ia] = packbf(lx,ly);
                *(uint32_t*)&o0[ib] = packbf(hz,hw);
                *(uint32_t*)&o1[ib] = packbf(lz,lw);
            }
        }
    }
}

// ---------------------------------------------------------------------------
// Fused attention: one CTA owns a full (bh, 128q) row-block.
// Phase A (cp.async pipeline): e = exp(qk/8)*mask written unnormalized to
//   attn, complete rowsums -> invS. Masked strips zero-filled.
// Phase B: re-reads its own e (L2-hot), normalizes attn in place,
//   ctx = (E @ V) * inv.
// ---------------------------------------------------------------------------
__global__ __launch_bounds__(256, 2) void attn_fused_kernel(
    const int* __restrict__ length, float* __restrict__ attn, float* __restrict__ ctx)
{
    __shared__ uint32_t SM[10240];   // A: As[2][2560]|Bs[2][2560]. B: As0|As1|Bs0|Bs1
    __shared__ float rs[128][2];
    __shared__ float invS[128];

    const int tid  = threadIdx.x;
    const int wid  = tid >> 5;
    const int lane = tid & 31;
    const int gid  = lane >> 2;
    const int tig  = lane & 3;
    const int wm   = wid >> 1;
    const int wn   = wid & 1;
    const int bh = blockIdx.y;
    const int b  = bh >> 4;
    const int h  = bh & 15;
    const int q0 = blockIdx.x * 128;

    const int len = length[b];
    int nsub = (len + 127) >> 7;
    if (nsub > 4) nsub = 4;
    const int total = nsub * 6;

    const int r0 = tid >> 3;
    const int c4 = tid & 7;

    // ======================= Phase A: scores =======================
    {
        uint32_t* pA = SM;
        uint32_t* pB = SM + 5120;
        const uint32_t sSM = (uint32_t)__cvta_generic_to_shared(SM);

        const __nv_bfloat16* qs[2] = { g_qb0 + ((size_t)bh*Sn + q0)*DKn,
                                       g_qb1 + ((size_t)bh*Sn + q0)*DKn };
        const __nv_bfloat16* kb[2] = { g_kb0 + (size_t)bh*Sn*DKn,
                                       g_kb1 + (size_t)bh*Sn*DKn };
        const int pa[3]  = {0, 0, 1};
        const int pb3[3] = {0, 1, 0};

        float4 acc[2][8];
#pragma unroll
        for (int mt = 0; mt < 2; mt++)
#pragma unroll
            for (int nt = 0; nt < 8; nt++) acc[mt][nt] = make_float4(0.f, 0.f, 0.f, 0.f);
        float rp[2][2] = {{0.f, 0.f}, {0.f, 0.f}};

        // preload stage 0 (sub 0, product 0, kc 0)
        {
            const __nv_bfloat16* a = qs[0];
            const __nv_bfloat16* w = kb[0];
#pragma unroll
            for (int j = 0; j < 4; j++) {
                int row = r0 + j*32;
                uint32_t wo = (uint32_t)(row*SA + c4*2) * 4;
                cpa8(sSM + wo,           a + (size_t)row*DKn + c4*4);
                cpa8(sSM + 5120*4 + wo,  w + (size_t)row*DKn + c4*4);
            }
        }
        CP_COMMIT();
        CP_WAIT0();
        __syncthreads();

        for (int gi = 0; gi < total; gi++) {
            const int cur = gi & 1;
            if (gi + 1 < total) {
                int g1  = gi + 1;
                int sub = g1 / 6;
                int qq  = g1 - sub*6;
                int p   = qq >> 1;
                int kc  = (qq & 1) * 32;
                const __nv_bfloat16* a = qs[pa[p]] + kc;
                const __nv_bfloat16* w = kb[pb3[p]] + (size_t)(sub << 7)*DKn + kc;
                const uint32_t soff = (uint32_t)(((gi + 1) & 1) * 2560) * 4;
#pragma unroll
                for (int j = 0; j < 4; j++) {
                    int row = r0 + j*32;
                    uint32_t wo = soff + (uint32_t)(row*SA + c4*2) * 4;
                    cpa8(sSM + wo,          a + (size_t)row*DKn + c4*4);
                    cpa8(sSM + 5120*4 + wo, w + (size_t)row*DKn + c4*4);
                }
                CP_COMMIT();
            }
#pragma unroll
            for (int s = 0; s < 2; s++) {
                uint32_t af[2][4];
#pragma unroll
                for (int mt = 0; mt < 2; mt++) {
                    int base = cur*2560 + (wm*32 + mt*16 + gid)*SA + s*8 + tig;
                    af[mt][0] = pA[base];
                    af[mt][1] = pA[base + 8*SA];
                    af[mt][2] = pA[base + 4];
                    af[mt][3] = pA[base + 8*SA + 4];
                }
#pragma unroll
                for (int nt = 0; nt < 8; nt++) {
                    int nb = cur*2560 + (wn*64 + nt*8 + gid)*SA + s*8 + tig;
                    uint32_t b0 = pB[nb];
                    uint32_t b1 = pB[nb + 4];
                    mma_bf16(acc[0][nt], af[0], b0, b1);
                    mma_bf16(acc[1][nt], af[1], b0, b1);
                }
            }
            if ((gi % 6) == 5) {
                const int k0 = (gi / 6) << 7;
#pragma unroll
                for (int mt = 0; mt < 2; mt++) {
                    int sa = q0 + wm*32 + mt*16 + gid;
                    int sb = sa + 8;
#pragma unroll
                    for (int nt = 0; nt < 8; nt++) {
                        int kc0 = k0 + wn*64 + nt*8 + tig*2;
                        float4 a = acc[mt][nt];
                        float ex = (kc0   < len) ? __expf(a.x * 0.125f) : 0.f;
                        float ey = (kc0+1 < len) ? __expf(a.y * 0.125f) : 0.f;
                        float ez = (kc0   < len) ? __expf(a.z * 0.125f) : 0.f;
                        float ew = (kc0+1 < len) ? __expf(a.w * 0.125f) : 0.f;
                        *(float2*)&attn[((size_t)bh*Sn + sa)*Sn + kc0] = make_float2(ex, ey);
                        *(float2*)&attn[((size_t)bh*Sn + sb)*Sn + kc0] = make_float2(ez, ew);
                        rp[mt][0] += ex + ey;
                        rp[mt][1] += ez + ew;
                        acc[mt][nt] = make_float4(0.f, 0.f, 0.f, 0.f);
                    }
                }
            }
            if (gi + 1 < total) {
                CP_WAIT0();
                __syncthreads();
            }
        }

        // zero-fill fully masked strips
        for (int sub = nsub; sub < 4; sub++) {
            const int k0 = sub << 7;
            float4 z4 = make_float4(0.f, 0.f, 0.f, 0.f);
#pragma unroll
            for (int j = 0; j < 16; j++) {
                int f = tid + j*256;
                int row = f >> 5, cc = (f & 31) * 4;
                *(float4*)&attn[((size_t)bh*Sn + q0 + row)*Sn + k0 + cc] = z4;
            }
        }

        // rowsums -> invS
#pragma unroll
        for (int mt = 0; mt < 2; mt++) {
            rp[mt][0] += __shfl_xor_sync(0xffffffffu, rp[mt][0], 1);
            rp[mt][0] += __shfl_xor_sync(0xffffffffu, rp[mt][0], 2);
            rp[mt][1] += __shfl_xor_sync(0xffffffffu, rp[mt][1], 1);
            rp[mt][1] += __shfl_xor_sync(0xffffffffu, rp[mt][1], 2);
            if (tig == 0) {
                int ra = wm*32 + mt*16 + gid;
                rs[ra][wn]     = rp[mt][0];
                rs[ra + 8][wn] = rp[mt][1];
            }
        }
        __syncthreads();
        if (tid < 128)
            invS[tid] = 1.0f / (rs[tid][0] + rs[tid][1] + 1e-8f);
    }

    // ======================= Phase B: av =======================
    {
        uint32_t* As0 = SM;
        uint32_t* As1 = SM + 2560;
        uint32_t* Bs0 = SM + 5120;
        uint32_t* Bs1 = SM + 6400;

        float* Ah = attn + ((size_t)bh*Sn + q0) * Sn;
        const __nv_bfloat16* vt0 = g_vt0 + (size_t)bh * DKn * Sn;
        const __nv_bfloat16* vt1 = g_vt1 + (size_t)bh * DKn * Sn;

        int kmax = (len + 31) & ~31;
        if (kmax > Sn) kmax = Sn;

        float4 accB[8];
#pragma unroll
        for (int nt = 0; nt < 8; nt++) accB[nt] = make_float4(0.f, 0.f, 0.f, 0.f);

        float4 avr[4];
        uint2 b0r[2], b1r[2];
#pragma unroll
        for (int j = 0; j < 4; j++) {
            int f = tid + j*256;
            int row = f >> 3, cc = f & 7;
            avr[j] = *(const float4*)(Ah + (size_t)row*Sn + 0 + cc*4);
        }
#pragma unroll
        for (int j = 0; j < 2; j++) {
            int g = tid + j*256;
            int row = g >> 3, cc = g & 7;
            b0r[j] = *(const uint2*)(vt0 + (size_t)row*Sn + 0 + cc*4);
            b1r[j] = *(const uint2*)(vt1 + (size_t)row*Sn + 0 + cc*4);
        }

        for (int kc = 0; kc < kmax; kc += 32) {
            __syncthreads();
#pragma unroll
            for (int j = 0; j < 4; j++) {
                int f = tid + j*256;
                int row = f >> 3, cc = f & 7;
                float iv = invS[row];
                float4 vv = avr[j];
                vv.x *= iv; vv.y *= iv; vv.z *= iv; vv.w *= iv;
                *(float4*)(Ah + (size_t)row*Sn + kc + cc*4) = vv;
                __nv_bfloat16 h0,l0,h1,l1,h2,l2,h3,l3;
                bsplit(vv.x,h0,l0); bsplit(vv.y,h1,l1); bsplit(vv.z,h2,l2); bsplit(vv.w,h3,l3);
                int wo = row*SA + cc*2;
                As0[wo]   = packbf(h0,h1); As0[wo+1] = packbf(h2,h3);
                As1[wo]   = packbf(l0,l1); As1[wo+1] = packbf(l2,l3);
            }
#pragma unroll
            for (int j = 0; j < 2; j++) {
                int g = tid + j*256;
                int row = g >> 3, cc = g & 7;
                int wo = row*SA + cc*2;
                *(uint2*)&Bs0[wo] = b0r[j];
                *(uint2*)&Bs1[wo] = b1r[j];
            }
            __syncthreads();

            if (kc + 32 < kmax) {
#pragma unroll
                for (int j = 0; j < 4; j++) {
                    int f = tid + j*256;
                    int row = f >> 3, cc = f & 7;
                    avr[j] = *(const float4*)(Ah + (size_t)row*Sn + kc + 32 + cc*4);
                }
#pragma unroll
                for (int j = 0; j < 2; j++) {
                    int g = tid + j*256;
                    int row = g >> 3, cc = g & 7;
                    b0r[j] = *(const uint2*)(vt0 + (size_t)row*Sn + kc + 32 + cc*4);
                    b1r[j] = *(const uint2*)(vt1 + (size_t)row*Sn + kc + 32 + cc*4);
                }
            }

#pragma unroll
            for (int s = 0; s < 2; s++) {
                uint32_t af0[4], af1[4];
                int base = (wid*16 + gid)*SA + s*8 + tig;
                af0[0] = As0[base];        af0[1] = As0[base + 8*SA];
                af0[2] = As0[base + 4];    af0[3] = As0[base + 8*SA + 4];
                af1[0] = As1[base];        af1[1] = As1[base + 8*SA];
                af1[2] = As1[base + 4];    af1[3] = As1[base + 8*SA + 4];
#pragma unroll
                for (int nt = 0; nt < 8; nt++) {
                    int nb = (nt*8 + gid)*SA + s*8 + tig;
                    uint32_t b00 = Bs0[nb], b01 = Bs0[nb + 4];
                    uint32_t b10 = Bs1[nb], b11 = Bs1[nb + 4];
                    mma_bf16(accB[nt], af0, b00, b01);   // a0*v0
                    mma_bf16(accB[nt], af0, b10, b11);   // a0*v1
                    mma_bf16(accB[nt], af1, b00, b01);   // a1*v0
                }
            }
        }

        int sa = q0 + wid*16 + gid;
        int sb = sa + 8;
#pragma unroll
        for (int nt = 0; nt < 8; nt++) {
            int dk = nt*8 + tig*2;
            *(float2*)&ctx[((size_t)(b*Sn + sa))*Dn + h*DKn + dk] = make_float2(accB[nt].x, accB[nt].y);
            *(float2*)&ctx[((size_t)(b*Sn + sb))*Dn + h*DKn + dk] = make_float2(accB[nt].z, accB[nt].w);
        }
    }
}

// ---------------------------------------------------------------------------
extern "C" void kernel_launch(void* const* d_in, const int* in_sizes, int n_in,
                              void* d_out, int out_size)
{
    const float* Q   = (const float*)d_in[0];
    const float* Wq  = (const float*)d_in[1];
    const float* bq  = (const float*)d_in[2];
    const float* Wk  = (const float*)d_in[3];
    const float* bk  = (const float*)d_in[4];
    const float* Wv  = (const float*)d_in[5];
    const float* bv  = (const float*)d_in[6];
    const int*   len = (const int*)d_in[7];

    float* ctx = (float*)d_out;
    float* attn;
    if ((size_t)out_size >= (size_t)CTX_ELEMS + ATT_ELEMS) {
        attn = ctx + CTX_ELEMS;   // tuple output: [context | attn]
    } else {
        void* p = nullptr;
        cudaGetSymbolAddress(&p, g_attn_fallback);
        attn = (float*)p;
    }

    // 0) bf16 hi/lo splits of inputs (single kernel)
    prep_kernel<<<dim3((XF4 + WF4 + 255)/256), 256>>>(Q, Wq, Wk, Wv);
    // 1) QKV projections (cp.async pipeline); dead K/V tiles skipped;
    //    V^T bf16 splits written directly
    qkv_mma_kernel<<<dim3(Dn/128, Mtot/128, 3), 256>>>(bq, bk, bv, len);
    // 2) fused scores + normalize + av (cp.async phase A, L2-hot phase B)
    attn_fused_kernel<<<dim3(Sn/128, BH), 256>>>(len, attn, ctx);
}

// round 17
// speedup vs baseline: 1.0149x; 1.0149x over previous
#include <cuda_runtime.h>
#include <cuda_bf16.h>
#include <math.h>
#include <stdint.h>

#define Bn   32
#define Sn   512
#define Dn   1024
#define Hn   16
#define DKn  64
#define BH   (Bn*Hn)                 // 512
#define Mtot (Bn*Sn)                 // 16384
#define CTX_ELEMS (Bn*Sn*Dn)         // 16,777,216
#define ATT_ELEMS ((size_t)Bn*Hn*Sn*Sn) // 134,217,728

// Scratch (allocation-free per harness rules)
__device__ float g_attn_fallback[ATT_ELEMS];
// bf16 hi/lo splits
__device__ __nv_bfloat16 g_xb0[CTX_ELEMS];
__device__ __nv_bfloat16 g_xb1[CTX_ELEMS];
__device__ __nv_bfloat16 g_wb0[3*Dn*Dn];
__device__ __nv_bfloat16 g_wb1[3*Dn*Dn];
__device__ __nv_bfloat16 g_qb0[CTX_ELEMS];
__device__ __nv_bfloat16 g_qb1[CTX_ELEMS];
__device__ __nv_bfloat16 g_kb0[CTX_ELEMS];
__device__ __nv_bfloat16 g_kb1[CTX_ELEMS];
__device__ __nv_bfloat16 g_vt0[CTX_ELEMS];   // V^T: [bh][dk=64][s=512]
__device__ __nv_bfloat16 g_vt1[CTX_ELEMS];

// ---------------- mma.sync bf16 (non-'a' tensor path, works on sm_103) -----
__device__ __forceinline__ void mma_bf16(float4& d, const uint32_t* a,
                                         uint32_t b0, uint32_t b1) {
    asm volatile(
        "mma.sync.aligned.m16n8k16.row.col.f32.bf16.bf16.f32 "
        "{%0,%1,%2,%3},{%4,%5,%6,%7},{%8,%9},{%0,%1,%2,%3};"
        : "+f"(d.x), "+f"(d.y), "+f"(d.z), "+f"(d.w)
        : "r"(a[0]), "r"(a[1]), "r"(a[2]), "r"(a[3]), "r"(b0), "r"(b1));
}

__device__ __forceinline__ void bsplit(float v, __nv_bfloat16& h, __nv_bfloat16& l) {
    h = __float2bfloat16(v);
    l = __float2bfloat16(v - __bfloat162float(h));
}
__device__ __forceinline__ uint32_t packbf(__nv_bfloat16 a, __nv_bfloat16 b) {
    __nv_bfloat162 t(a, b);
    return *(uint32_t*)&t;
}

// ---------------- cp.async helpers (sm_80+, valid on non-'a' sm_103) -------
__device__ __forceinline__ void cpa8(uint32_t saddr, const void* g) {
    asm volatile("cp.async.ca.shared.global [%0], [%1], 8;"
                 :: "r"(saddr), "l"(g) : "memory");
}
#define CP_COMMIT() asm volatile("cp.async.commit_group;" ::: "memory")
#define CP_WAIT0()  asm volatile("cp.async.wait_group 0;" ::: "memory")

// ---------------------------------------------------------------------------
// prep: bf16 hi/lo splits of X and the 3 weight matrices (single kernel)
// ---------------------------------------------------------------------------
#define XF4 (CTX_ELEMS/4)            // 4,194,304 float4 in X
#define WF4 (3*Dn*Dn/4)              // 786,432 float4 in W

__global__ __launch_bounds__(256) void prep_kernel(
    const float* __restrict__ X,
    const float* __restrict__ Wq, const float* __restrict__ Wk, const float* __restrict__ Wv)
{
    size_t i = (size_t)blockIdx.x * 256 + threadIdx.x;
    if (i < XF4) {
        float4 v = ((const float4*)X)[i];
        float f[4] = {v.x, v.y, v.z, v.w};
        __nv_bfloat16 b0[4], b1[4];
#pragma unroll
        for (int k = 0; k < 4; k++) bsplit(f[k], b0[k], b1[k]);
        ((uint32_t*)g_xb0)[i*2]   = packbf(b0[0], b0[1]);
        ((uint32_t*)g_xb0)[i*2+1] = packbf(b0[2], b0[3]);
        ((uint32_t*)g_xb1)[i*2]   = packbf(b1[0], b1[1]);
        ((uint32_t*)g_xb1)[i*2+1] = packbf(b1[2], b1[3]);
    } else {
        size_t j = i - XF4;
        if (j >= WF4) return;
        int z = (int)(j >> 18);
        const float* src = (z == 0) ? Wq : (z == 1) ? Wk : Wv;
        float4 v = ((const float4*)src)[j & 262143];
        float f[4] = {v.x, v.y, v.z, v.w};
        __nv_bfloat16 b0[4], b1[4];
#pragma unroll
        for (int k = 0; k < 4; k++) bsplit(f[k], b0[k], b1[k]);
        ((uint32_t*)g_wb0)[j*2]   = packbf(b0[0], b0[1]);
        ((uint32_t*)g_wb0)[j*2+1] = packbf(b0[2], b0[3]);
        ((uint32_t*)g_wb1)[j*2]   = packbf(b1[0], b1[1]);
        ((uint32_t*)g_wb1)[j*2+1] = packbf(b1[2], b1[3]);
    }
}

// ---------------------------------------------------------------------------
// QKV projection via mma.sync bf16x3: C = X @ W^T + bias
// cp.async double-buffered pipeline. Dead K/V tiles early-exit.
// z=2 (V) writes V^T bf16 hi/lo splits directly (smem-staged transpose).
// ---------------------------------------------------------------------------
#define SA 20   // smem row stride in words

__global__ __launch_bounds__(256, 2) void qkv_mma_kernel(
    const float* __restrict__ bq, const float* __restrict__ bk, const float* __restrict__ bv,
    const int* __restrict__ length)
{
    __shared__ uint32_t As[2][128*SA];
    __shared__ uint32_t Bs[2][128*SA];

    const int tid  = threadIdx.x;
    const int wid  = tid >> 5;
    const int lane = tid & 31;
    const int gid  = lane >> 2;
    const int tig  = lane & 3;
    const int wm   = wid >> 1;
    const int wn   = wid & 1;
    const int z    = blockIdx.z;
    const int bm   = blockIdx.y * 128;
    const int bn   = blockIdx.x * 128;

    if (z >= 1) {
        if ((bm & 511) >= length[bm >> 9]) return;
    }

    const size_t zoff = (size_t)z * Dn * Dn;
    const __nv_bfloat16* w0p = g_wb0 + zoff;
    const __nv_bfloat16* w1p = g_wb1 + zoff;

    const int r0 = tid >> 3;
    const int c4 = tid & 7;

    const uint32_t sA = (uint32_t)__cvta_generic_to_shared(&As[0][0]);
    const uint32_t sB = (uint32_t)__cvta_generic_to_shared(&Bs[0][0]);

    float4 acc[2][8];
#pragma unroll
    for (int mt = 0; mt < 2; mt++)
#pragma unroll
        for (int nt = 0; nt < 8; nt++) acc[mt][nt] = make_float4(0.f, 0.f, 0.f, 0.f);

    {
        const __nv_bfloat16* a = g_xb0 + (size_t)bm * Dn;
        const __nv_bfloat16* w = w0p   + (size_t)bn * Dn;
#pragma unroll
        for (int j = 0; j < 4; j++) {
            int row = r0 + j*32;
            uint32_t wo = (uint32_t)(row*SA + c4*2) * 4;
            cpa8(sA + wo, a + (size_t)row*Dn + c4*4);
            cpa8(sB + wo, w + (size_t)row*Dn + c4*4);
        }
    }
    CP_COMMIT();
    CP_WAIT0();
    __syncthreads();

    for (int it = 0; it < 96; it++) {
        const int cur = it & 1;
        if (it + 1 < 96) {
            int p  = (it + 1) >> 5;
            int kc = ((it + 1) & 31) * 32;
            const __nv_bfloat16* a = ((p == 2) ? g_xb1 : g_xb0) + (size_t)bm * Dn + kc;
            const __nv_bfloat16* w = ((p == 1) ? w1p  : w0p  ) + (size_t)bn * Dn + kc;
            const uint32_t soff = (uint32_t)(((it + 1) & 1) * 2560) * 4;
#pragma unroll
            for (int j = 0; j < 4; j++) {
                int row = r0 + j*32;
                uint32_t wo = soff + (uint32_t)(row*SA + c4*2) * 4;
                cpa8(sA + wo, a + (size_t)row*Dn + c4*4);
                cpa8(sB + wo, w + (size_t)row*Dn + c4*4);
            }
            CP_COMMIT();
        }
#pragma unroll
        for (int s = 0; s < 2; s++) {
            uint32_t af[2][4];
#pragma unroll
            for (int mt = 0; mt < 2; mt++) {
                int base = (wm*32 + mt*16 + gid)*SA + s*8 + tig;
                af[mt][0] = As[cur][base];
                af[mt][1] = As[cur][base + 8*SA];
                af[mt][2] = As[cur][base + 4];
                af[mt][3] = As[cur][base + 8*SA + 4];
            }
#pragma unroll
            for (int nt = 0; nt < 8; nt++) {
                int nb = (wn*64 + nt*8 + gid)*SA + s*8 + tig;
                uint32_t b0 = Bs[cur][nb];
                uint32_t b1 = Bs[cur][nb + 4];
                mma_bf16(acc[0][nt], af[0], b0, b1);
                mma_bf16(acc[1][nt], af[1], b0, b1);
            }
        }
        if (it + 1 < 96) {
            CP_WAIT0();
            __syncthreads();
        }
    }

    const float* bias = (z == 0) ? bq : (z == 1) ? bk : bv;
    if (z == 2) {
        const int b  = bm >> 9;
        const int s0 = bm & 511;
        const int h0 = bn >> 6;
        uint16_t* Vh = (uint16_t*)&As[0][0];
        uint16_t* Vl = Vh + 64*132;
        __syncthreads();
#pragma unroll
        for (int ph = 0; ph < 2; ph++) {
            if (wn == ph) {
#pragma unroll
                for (int mt = 0; mt < 2; mt++) {
                    int ra = wm*32 + mt*16 + gid;
                    int rb = ra + 8;
#pragma unroll
                    for (int nt = 0; nt < 8; nt++) {
                        int fl = nt*8 + tig*2;
                        int feat = bn + ph*64 + fl;
                        float2 bv2 = *(const float2*)&bias[feat];
                        float vx = acc[mt][nt].x + bv2.x, vy = acc[mt][nt].y + bv2.y;
                        float vz = acc[mt][nt].z + bv2.x, vw = acc[mt][nt].w + bv2.y;
                        __nv_bfloat16 hx,lx,hy,ly,hz,lz,hw,lw;
                        bsplit(vx,hx,lx); bsplit(vy,hy,ly);
                        bsplit(vz,hz,lz); bsplit(vw,hw,lw);
                        Vh[fl*132 + ra]     = *(uint16_t*)&hx;
                        Vl[fl*132 + ra]     = *(uint16_t*)&lx;
                        Vh[(fl+1)*132 + ra] = *(uint16_t*)&hy;
                        Vl[(fl+1)*132 + ra] = *(uint16_t*)&ly;
                        Vh[fl*132 + rb]     = *(uint16_t*)&hz;
                        Vl[fl*132 + rb]     = *(uint16_t*)&lz;
                        Vh[(fl+1)*132 + rb] = *(uint16_t*)&hw;
                        Vl[(fl+1)*132 + rb] = *(uint16_t*)&lw;
                    }
                }
            }
            __syncthreads();
            const size_t base = ((size_t)((b*Hn + h0 + ph))*DKn)*Sn + s0;
#pragma unroll
            for (int j = 0; j < 16; j++) {
                int w = tid + j*256;
                int dk = w >> 6;
                int sw = (w & 63) * 2;
                uint32_t vh = *(uint32_t*)&Vh[dk*132 + sw];
                uint32_t vl = *(uint32_t*)&Vl[dk*132 + sw];
                *(uint32_t*)&g_vt0[base + (size_t)dk*Sn + sw] = vh;
                *(uint32_t*)&g_vt1[base + (size_t)dk*Sn + sw] = vl;
            }
            __syncthreads();
        }
    } else {
        __nv_bfloat16* o0 = (z == 0) ? g_qb0 : g_kb0;
        __nv_bfloat16* o1 = (z == 0) ? g_qb1 : g_kb1;
#pragma unroll
        for (int mt = 0; mt < 2; mt++) {
            int rowa = bm + wm*32 + mt*16 + gid;
            int rowb = rowa + 8;
            int ba = rowa >> 9, sa = rowa & 511;
            int bb2 = rowb >> 9, sb = rowb & 511;
#pragma unroll
            for (int nt = 0; nt < 8; nt++) {
                int feat = bn + wn*64 + nt*8 + tig*2;
                int h = feat >> 6, dk = feat & 63;
                float2 bv2 = *(const float2*)&bias[feat];
                float vx = acc[mt][nt].x + bv2.x, vy = acc[mt][nt].y + bv2.y;
                float vz = acc[mt][nt].z + bv2.x, vw = acc[mt][nt].w + bv2.y;
                __nv_bfloat16 hx,lx,hy,ly,hz,lz,hw,lw;
                bsplit(vx,hx,lx); bsplit(vy,hy,ly); bsplit(vz,hz,lz); bsplit(vw,hw,lw);
                size_t ia = ((size_t)((ba *Hn + h)*Sn + sa))*DKn + dk;
                size_t ib = ((size_t)((bb2*Hn + h)*Sn + sb))*DKn + dk;
                *(uint32_t*)&o0[ia] = packbf(hx,hy);
                *(uint32_t*)&o1[ia] = packbf(lx,ly);
                *(uint32_t*)&o0[ib] = packbf(hz,hw);
                *(uint32_t*)&o1[ib] = packbf(lz,lw);
            }
        }
    }
}

// ---------------------------------------------------------------------------
// Fused attention, Q-resident: one CTA owns a (bh, 128q) row-block.
// Phase A: Q (both splits) loaded ONCE into smem (stride 36); K tiles
//   double-buffered via cp.async. e written unnormalized; rowsums -> invS.
// Phase B: re-reads own e (L2-hot), normalizes in place, ctx = (E@V)*inv.
// Dynamic smem: 14336 words = 56 KB (occ 2).
// ---------------------------------------------------------------------------
#define FUSED_SMEM (14336*4)

__global__ __launch_bounds__(256, 2) void attn_fused_kernel(
    const int* __restrict__ length, float* __restrict__ attn, float* __restrict__ ctx)
{
    extern __shared__ uint32_t SM[];   // A: Qs0[4608]|Qs1[4608]|Ks[2][2560]. B: As0|As1|Bs0|Bs1
    __shared__ float rs[128][2];
    __shared__ float invS[128];

    const int tid  = threadIdx.x;
    const int wid  = tid >> 5;
    const int lane = tid & 31;
    const int gid  = lane >> 2;
    const int tig  = lane & 3;
    const int wm   = wid >> 1;
    const int wn   = wid & 1;
    const int bh = blockIdx.y;
    const int b  = bh >> 4;
    const int h  = bh & 15;
    const int q0 = blockIdx.x * 128;

    const int len = length[b];
    int nsub = (len + 127) >> 7;
    if (nsub > 4) nsub = 4;
    const int total = nsub * 6;

    // ======================= Phase A: scores =======================
    {
        uint32_t* Qs0 = SM;
        uint32_t* Qs1 = SM + 4608;
        uint32_t* Ks  = SM + 9216;
        const uint32_t sBase = (uint32_t)__cvta_generic_to_shared(SM);

        const __nv_bfloat16* kb[2] = { g_kb0 + (size_t)bh*Sn*DKn,
                                       g_kb1 + (size_t)bh*Sn*DKn };
        const int pb3[3] = {0, 1, 0};

        float4 acc[2][8];
#pragma unroll
        for (int mt = 0; mt < 2; mt++)
#pragma unroll
            for (int nt = 0; nt < 8; nt++) acc[mt][nt] = make_float4(0.f, 0.f, 0.f, 0.f);
        float rp[2][2] = {{0.f, 0.f}, {0.f, 0.f}};

        // load Q resident (both splits, 128 rows x 64 bf16, stride 36)
        {
            const __nv_bfloat16* q0p = g_qb0 + ((size_t)bh*Sn + q0)*DKn;
            const __nv_bfloat16* q1p = g_qb1 + ((size_t)bh*Sn + q0)*DKn;
#pragma unroll
            for (int j = 0; j < 8; j++) {
                int f = tid + j*256;              // 2048 uint2 sites per split
                int row = f >> 4, c2 = f & 15;
                uint32_t wo = (uint32_t)(row*36 + c2*2) * 4;
                cpa8(sBase + wo,           q0p + (size_t)row*DKn + c2*4);
                cpa8(sBase + 4608*4 + wo,  q1p + (size_t)row*DKn + c2*4);
            }
        }
        // preload K stage 0 (sub 0, k-split 0, kc 0)
        {
            const __nv_bfloat16* w = kb[0];
            const int r0 = tid >> 3, c4l = tid & 7;
#pragma unroll
            for (int j = 0; j < 4; j++) {
                int row = r0 + j*32;
                uint32_t wo = (uint32_t)(9216 + row*SA + c4l*2) * 4;
                cpa8(sBase + wo, w + (size_t)row*DKn + c4l*4);
            }
        }
        CP_COMMIT();
        CP_WAIT0();
        __syncthreads();

        for (int gi = 0; gi < total; gi++) {
            const int cur = gi & 1;
            const int sub_c = gi / 6;
            const int qqc = gi - sub_c*6;
            const int p_c = qqc >> 1;
            const int kcw = (qqc & 1) * 16;
            const uint32_t* Qp = (p_c == 2) ? Qs1 : Qs0;

            if (gi + 1 < total) {
                int g1  = gi + 1;
                int sub = g1 / 6;
                int qq  = g1 - sub*6;
                int p   = qq >> 1;
                int kc  = (qq & 1) * 32;
                const __nv_bfloat16* w = kb[pb3[p]] + (size_t)(sub << 7)*DKn + kc;
                const uint32_t soff = (uint32_t)(9216 + ((gi + 1) & 1) * 2560) * 4;
                const int r0 = tid >> 3, c4l = tid & 7;
#pragma unroll
                for (int j = 0; j < 4; j++) {
                    int row = r0 + j*32;
                    uint32_t wo = soff + (uint32_t)(row*SA + c4l*2) * 4;
                    cpa8(sBase + wo, w + (size_t)row*DKn + c4l*4);
                }
                CP_COMMIT();
            }
#pragma unroll
            for (int s = 0; s < 2; s++) {
                uint32_t af[2][4];
#pragma unroll
                for (int mt = 0; mt < 2; mt++) {
                    int base = (wm*32 + mt*16 + gid)*36 + kcw + s*8 + tig;
                    af[mt][0] = Qp[base];
                    af[mt][1] = Qp[base + 8*36];
                    af[mt][2] = Qp[base + 4];
                    af[mt][3] = Qp[base + 8*36 + 4];
                }
#pragma unroll
                for (int nt = 0; nt < 8; nt++) {
                    int nb = cur*2560 + (wn*64 + nt*8 + gid)*SA + s*8 + tig;
                    uint32_t b0 = Ks[nb];
                    uint32_t b1 = Ks[nb + 4];
                    mma_bf16(acc[0][nt], af[0], b0, b1);
                    mma_bf16(acc[1][nt], af[1], b0, b1);
                }
            }
            if (qqc == 5) {
                const int k0 = sub_c << 7;
#pragma unroll
                for (int mt = 0; mt < 2; mt++) {
                    int sa = q0 + wm*32 + mt*16 + gid;
                    int sb = sa + 8;
#pragma unroll
                    for (int nt = 0; nt < 8; nt++) {
                        int kc0 = k0 + wn*64 + nt*8 + tig*2;
                        float4 a = acc[mt][nt];
                        float ex = (kc0   < len) ? __expf(a.x * 0.125f) : 0.f;
                        float ey = (kc0+1 < len) ? __expf(a.y * 0.125f) : 0.f;
                        float ez = (kc0   < len) ? __expf(a.z * 0.125f) : 0.f;
                        float ew = (kc0+1 < len) ? __expf(a.w * 0.125f) : 0.f;
                        *(float2*)&attn[((size_t)bh*Sn + sa)*Sn + kc0] = make_float2(ex, ey);
                        *(float2*)&attn[((size_t)bh*Sn + sb)*Sn + kc0] = make_float2(ez, ew);
                        rp[mt][0] += ex + ey;
                        rp[mt][1] += ez + ew;
                        acc[mt][nt] = make_float4(0.f, 0.f, 0.f, 0.f);
                    }
                }
            }
            if (gi + 1 < total) {
                CP_WAIT0();
                __syncthreads();
            }
        }

        // zero-fill fully masked strips
        for (int sub = nsub; sub < 4; sub++) {
            const int k0 = sub << 7;
            float4 z4 = make_float4(0.f, 0.f, 0.f, 0.f);
#pragma unroll
            for (int j = 0; j < 16; j++) {
                int f = tid + j*256;
                int row = f >> 5, cc = (f & 31) * 4;
                *(float4*)&attn[((size_t)bh*Sn + q0 + row)*Sn + k0 + cc] = z4;
            }
        }

        // rowsums -> invS
#pragma unroll
        for (int mt = 0; mt < 2; mt++) {
            rp[mt][0] += __shfl_xor_sync(0xffffffffu, rp[mt][0], 1);
            rp[mt][0] += __shfl_xor_sync(0xffffffffu, rp[mt][0], 2);
            rp[mt][1] += __shfl_xor_sync(0xffffffffu, rp[mt][1], 1);
            rp[mt][1] += __shfl_xor_sync(0xffffffffu, rp[mt][1], 2);
            if (tig == 0) {
                int ra = wm*32 + mt*16 + gid;
                rs[ra][wn]     = rp[mt][0];
                rs[ra + 8][wn] = rp[mt][1];
            }
        }
        __syncthreads();
        if (tid < 128)
            invS[tid] = 1.0f / (rs[tid][0] + rs[tid][1] + 1e-8f);
    }

    // ======================= Phase B: av =======================
    {
        uint32_t* As0 = SM;
        uint32_t* As1 = SM + 2560;
        uint32_t* Bs0 = SM + 5120;
        uint32_t* Bs1 = SM + 6400;

        float* Ah = attn + ((size_t)bh*Sn + q0) * Sn;
        const __nv_bfloat16* vt0 = g_vt0 + (size_t)bh * DKn * Sn;
        const __nv_bfloat16* vt1 = g_vt1 + (size_t)bh * DKn * Sn;

        int kmax = (len + 31) & ~31;
        if (kmax > Sn) kmax = Sn;

        float4 accB[8];
#pragma unroll
        for (int nt = 0; nt < 8; nt++) accB[nt] = make_float4(0.f, 0.f, 0.f, 0.f);

        float4 avr[4];
        uint2 b0r[2], b1r[2];
#pragma unroll
        for (int j = 0; j < 4; j++) {
            int f = tid + j*256;
            int row = f >> 3, cc = f & 7;
            avr[j] = *(const float4*)(Ah + (size_t)row*Sn + 0 + cc*4);
        }
#pragma unroll
        for (int j = 0; j < 2; j++) {
            int g = tid + j*256;
            int row = g >> 3, cc = g & 7;
            b0r[j] = *(const uint2*)(vt0 + (size_t)row*Sn + 0 + cc*4);
            b1r[j] = *(const uint2*)(vt1 + (size_t)row*Sn + 0 + cc*4);
        }

        for (int kc = 0; kc < kmax; kc += 32) {
            __syncthreads();
#pragma unroll
            for (int j = 0; j < 4; j++) {
                int f = tid + j*256;
                int row = f >> 3, cc = f & 7;
                float iv = invS[row];
                float4 vv = avr[j];
                vv.x *= iv; vv.y *= iv; vv.z *= iv; vv.w *= iv;
                *(float4*)(Ah + (size_t)row*Sn + kc + cc*4) = vv;
                __nv_bfloat16 h0,l0,h1,l1,h2,l2,h3,l3;
                bsplit(vv.x,h0,l0); bsplit(vv.y,h1,l1); bsplit(vv.z,h2,l2); bsplit(vv.w,h3,l3);
                int wo = row*SA + cc*2;
                As0[wo]   = packbf(h0,h1); As0[wo+1] = packbf(h2,h3);
                As1[wo]   = packbf(l0,l1); As1[wo+1] = packbf(l2,l3);
            }
#pragma unroll
            for (int j = 0; j < 2; j++) {
                int g = tid + j*256;
                int row = g >> 3, cc = g & 7;
                int wo = row*SA + cc*2;
                *(uint2*)&Bs0[wo] = b0r[j];
                *(uint2*)&Bs1[wo] = b1r[j];
            }
            __syncthreads();

            if (kc + 32 < kmax) {
#pragma unroll
                for (int j = 0; j < 4; j++) {
                    int f = tid + j*256;
                    int row = f >> 3, cc = f & 7;
                    avr[j] = *(const float4*)(Ah + (size_t)row*Sn + kc + 32 + cc*4);
                }
#pragma unroll
                for (int j = 0; j < 2; j++) {
                    int g = tid + j*256;
                    int row = g >> 3, cc = g & 7;
                    b0r[j] = *(const uint2*)(vt0 + (size_t)row*Sn + kc + 32 + cc*4);
                    b1r[j] = *(const uint2*)(vt1 + (size_t)row*Sn + kc + 32 + cc*4);
                }
            }

#pragma unroll
            for (int s = 0; s < 2; s++) {
                uint32_t af0[4], af1[4];
                int base = (wid*16 + gid)*SA + s*8 + tig;
                af0[0] = As0[base];        af0[1] = As0[base + 8*SA];
                af0[2] = As0[base + 4];    af0[3] = As0[base + 8*SA + 4];
                af1[0] = As1[base];        af1[1] = As1[base + 8*SA];
                af1[2] = As1[base + 4];    af1[3] = As1[base + 8*SA + 4];
#pragma unroll
                for (int nt = 0; nt < 8; nt++) {
                    int nb = (nt*8 + gid)*SA + s*8 + tig;
                    uint32_t b00 = Bs0[nb], b01 = Bs0[nb + 4];
                    uint32_t b10 = Bs1[nb], b11 = Bs1[nb + 4];
                    mma_bf16(accB[nt], af0, b00, b01);   // a0*v0
                    mma_bf16(accB[nt], af0, b10, b11);   // a0*v1
                    mma_bf16(accB[nt], af1, b00, b01);   // a1*v0
                }
            }
        }

        int sa = q0 + wid*16 + gid;
        int sb = sa + 8;
#pragma unroll
        for (int nt = 0; nt < 8; nt++) {
            int dk = nt*8 + tig*2;
            *(float2*)&ctx[((size_t)(b*Sn + sa))*Dn + h*DKn + dk] = make_float2(accB[nt].x, accB[nt].y);
            *(float2*)&ctx[((size_t)(b*Sn + sb))*Dn + h*DKn + dk] = make_float2(accB[nt].z, accB[nt].w);
        }
    }
}

// ---------------------------------------------------------------------------
extern "C" void kernel_launch(void* const* d_in, const int* in_sizes, int n_in,
                              void* d_out, int out_size)
{
    const float* Q   = (const float*)d_in[0];
    const float* Wq  = (const float*)d_in[1];
    const float* bq  = (const float*)d_in[2];
    const float* Wk  = (const float*)d_in[3];
    const float* bk  = (const float*)d_in[4];
    const float* Wv  = (const float*)d_in[5];
    const float* bv  = (const float*)d_in[6];
    const int*   len = (const int*)d_in[7];

    float* ctx = (float*)d_out;
    float* attn;
    if ((size_t)out_size >= (size_t)CTX_ELEMS + ATT_ELEMS) {
        attn = ctx + CTX_ELEMS;   // tuple output: [context | attn]
    } else {
        void* p = nullptr;
        cudaGetSymbolAddress(&p, g_attn_fallback);
        attn = (float*)p;
    }

    cudaFuncSetAttribute(attn_fused_kernel,
                         cudaFuncAttributeMaxDynamicSharedMemorySize, FUSED_SMEM);

    // 0) bf16 hi/lo splits of inputs (single kernel)
    prep_kernel<<<dim3((XF4 + WF4 + 255)/256), 256>>>(Q, Wq, Wk, Wv);
    // 1) QKV projections (cp.async pipeline); dead K/V tiles skipped;
    //    V^T bf16 splits written directly
    qkv_mma_kernel<<<dim3(Dn/128, Mtot/128, 3), 256>>>(bq, bk, bv, len);
    // 2) fused scores + normalize + av (Q resident in smem, K cp.async)
    attn_fused_kernel<<<dim3(Sn/128, BH), 256, FUSED_SMEM>>>(len, attn, ctx);
}